// round 16
// baseline (speedup 1.0000x reference)
#include <cuda_runtime.h>
#include <cuda_fp16.h>
#include <math.h>
#include <stdint.h>

#define N_LEVELS   16
#define N_DQ       9            // levels 0..8: dense fp16 quad grid
#define N_HQ       7            // levels 9..15: quad hash tables
#define HASH_BITS  19
#define TABLE_SIZE (1u << HASH_BITS)
#define HASH_MASK  (TABLE_SIZE - 1u)
#define PRIME2     2654435761u
#define PRIME3     805459861u
#define FSCALE     256.0f
#define INV_FSCALE (1.0f / 256.0f)

// Dense fp16 quad grid, levels 0..8: entry(cx,cy,cz) = 16B =
//   {h2(y0z0), h2(y0z1), h2(y1z0), h2(y1z1)}, h2 = half2(256*f0, 256*f1)
#define DQ_CAP 2200000
__device__ uint4 g_dq[DQ_CAP];                           // ~35 MB

// Quad hash tables for ALL 7 hashed levels (9..15):
//   T[s] = { h2(tab[s]), h2(tab[s+Dz]), h2(tab[s+Dy]), h2(tab[s+Dy+Dz]) }
//   Dz = P3*dM, Dy = P2*dM, dM = majority quantizer step = round-ish(2^17/res).
//   Mismatching lanes (wrap / minority delta) load neighbor ENTRIES and use
//   their exact .x/.y/.z words -> no fallback path needed, ever.
__device__ uint4 g_hq[(size_t)N_HQ << HASH_BITS];        // ~58.7 MB

struct Params {
    int      res[N_LEVELS];
    unsigned dA[N_LEVELS];       // hashed: Dz = P3*dM
    unsigned dB[N_LEVELS];       // hashed: Dy = P2*dM
    int      dq_prefix[N_DQ + 1];
    int      blocks_dq;
    int      total_dq, total_hq;
};

// XLA-GPU lowers f32 divide to div.full.f32 (approx). The hash trunc
// amplifies 1-ulp differences into wrong indices; reproduce the instruction.
__device__ __forceinline__ float div_full(float a, float b) {
    float r;
    asm("div.full.f32 %0, %1, %2;" : "=f"(r) : "f"(a), "f"(b));
    return r;
}

__device__ __forceinline__ unsigned hash_part(int c, float fres, unsigned prime) {
    float cfrac = div_full((float)c, fres);
    // (cfrac+1)*0.5*2^18 == (cfrac+1)*2^17 exactly (power-of-2 scalings exact)
    float qf = __fmul_rn(__fadd_rn(cfrac, 1.0f), 131072.0f);
    unsigned q = (unsigned)qf;            // positive -> trunc == astype(int64)
    return q * prime;                      // uint32 wrap OK: 2^19 | 2^32
}

__device__ __forceinline__ unsigned pack_h2(float2 v) {
    __half2 h = __floats2half2_rn(v.x * FSCALE, v.y * FSCALE);
    return *reinterpret_cast<unsigned*>(&h);
}
__device__ __forceinline__ float2 unpack_h2(unsigned u) {
    __half2 h = *reinterpret_cast<__half2*>(&u);
    return __half22float2(h);
}

__device__ __forceinline__ void stcs_f2(float2* p, float2 v) {
    asm volatile("st.global.cs.v2.f32 [%0], {%1, %2};"
                 :: "l"(p), "f"(v.x), "f"(v.y) : "memory");
}

// ---------------------------------------------------------------------------
// Fused fill kernel. Blocks [0, blocks_dq): dense grid (shfl path needs
// warp-uniform region). Remaining blocks: quad hash tables, fully coalesced.
// ---------------------------------------------------------------------------
__global__ void __launch_bounds__(256)
fill_all_kernel(const float* __restrict__ tables, Params p)
{
    int b = blockIdx.x;

    if (b < p.blocks_dq) {
        // ---- dense fp16 quad fill (levels 0..8) ----
        int tid0 = b * 256 + threadIdx.x;
        bool valid = tid0 < p.total_dq;
        int tid = valid ? tid0 : (p.total_dq - 1);

        int level = 0;
#pragma unroll
        for (int i = 0; i < N_DQ; i++)
            if (tid >= p.dq_prefix[i + 1]) level = i + 1;

        int r   = tid - p.dq_prefix[level];
        int res = p.res[level];
        int cz = r % res;
        int t  = r / res;
        int cy = t % res;
        int cx = t / res;
        int cy1 = (cy + 1 == res) ? 0 : cy + 1;

        float fres = (float)res;
        unsigned hx  = hash_part(cx,  fres, 1u);
        unsigned hy  = hash_part(cy,  fres, PRIME2);
        unsigned hy1 = hash_part(cy1, fres, PRIME2);
        unsigned hz  = hash_part(cz,  fres, PRIME3);

        const float2* tab = reinterpret_cast<const float2*>(tables)
                            + (size_t)level * TABLE_SIZE;
        float2 v00 = __ldg(tab + ((hx + hy  + hz) & HASH_MASK));
        float2 v10 = __ldg(tab + ((hx + hy1 + hz) & HASH_MASK));

        int lane = threadIdx.x & 31;
        float a0 = __shfl_down_sync(0xFFFFFFFFu, v00.x, 1);
        float a1 = __shfl_down_sync(0xFFFFFFFFu, v00.y, 1);
        float b0 = __shfl_down_sync(0xFFFFFFFFu, v10.x, 1);
        float b1 = __shfl_down_sync(0xFFFFFFFFu, v10.y, 1);
        float2 v01, v11;
        if (valid && cz < res - 1 && lane < 31 && tid0 + 1 < p.total_dq) {
            v01 = make_float2(a0, a1);
            v11 = make_float2(b0, b1);
        } else {
            int z1 = (cz + 1 == res) ? 0 : cz + 1;
            unsigned hz1 = hash_part(z1, fres, PRIME3);
            v01 = __ldg(tab + ((hx + hy  + hz1) & HASH_MASK));
            v11 = __ldg(tab + ((hx + hy1 + hz1) & HASH_MASK));
        }

        if (valid) {
            uint4 e;
            e.x = pack_h2(v00);
            e.y = pack_h2(v01);
            e.z = pack_h2(v10);
            e.w = pack_h2(v11);
            g_dq[(size_t)p.dq_prefix[level] + ((cx * res + cy) * res + cz)] = e;
        }
    } else {
        // ---- quad hash table fill (levels 9..15), coalesced 4-stream ----
        int tid = (b - p.blocks_dq) * 256 + threadIdx.x;
        if (tid >= p.total_hq) return;
        int slot   = tid >> HASH_BITS;       // 0..6
        unsigned s = tid & HASH_MASK;
        int lvl = N_DQ + slot;
        unsigned Dz = p.dA[lvl];
        unsigned Dy = p.dB[lvl];

        const float2* tab = reinterpret_cast<const float2*>(tables)
                            + (size_t)lvl * TABLE_SIZE;
        uint4 e;
        e.x = pack_h2(__ldg(tab + s));
        e.y = pack_h2(__ldg(tab + ((s + Dz) & HASH_MASK)));
        e.z = pack_h2(__ldg(tab + ((s + Dy) & HASH_MASK)));
        e.w = pack_h2(__ldg(tab + ((s + Dy + Dz) & HASH_MASK)));
        g_hq[((size_t)slot << HASH_BITS) + s] = e;
    }
}

// ---------------------------------------------------------------------------
// Main kernel: block = 32 points x 16 levels (512 threads).
// warp w = level w (branch-uniform), lane = point. Output via smem transpose.
// Hashed levels: general quad scheme, no fallback.
// ---------------------------------------------------------------------------
__global__ void __launch_bounds__(512)
hash_encoding_kernel(const float* __restrict__ x,
                     float* __restrict__ out,
                     Params p,
                     int n_points)
{
    __shared__ float4 xs4[32];                // padded point coords (w unused)
    __shared__ float  outs[32][33];           // stride 33 words: conflict-free

    int tid = threadIdx.x;
    int n0  = blockIdx.x * 32;

    if (tid < 96) {
        int gi = n0 * 3 + tid;
        float v = (gi < n_points * 3) ? __ldcs(&x[gi]) : 0.0f;
        reinterpret_cast<float*>(xs4)[(tid / 3) * 4 + (tid % 3)] = v;
    }
    __syncthreads();

    int level = tid >> 5;        // warp index == level (uniform per warp)
    int l     = tid & 31;        // point within block

    float4 pt = xs4[l];          // one LDS.128
    float xv[3];
    xv[0] = fminf(fmaxf(pt.x, -1.0f), 1.0f);
    xv[1] = fminf(fmaxf(pt.y, -1.0f), 1.0f);
    xv[2] = fminf(fmaxf(pt.z, -1.0f), 1.0f);

    const int   res  = p.res[level];
    const float fres = (float)res;

    int   c0[3], c1[3];
    float w[3][2];
#pragma unroll
    for (int d = 0; d < 3; d++) {
        float coord = xv[d] * fres;
        float cf    = floorf(coord);
        float lc    = coord - cf;
        int   ci    = (int)cf;
        w[d][0] = 1.0f - lc;
        w[d][1] = lc;
        // ci in [-res, res] -> floor-mod via predicated adds (no int div)
        int a = ci;
        if (a < 0)    a += res;
        if (a >= res) a -= res;
        c0[d] = a;
        int bb = a + 1; if (bb == res) bb = 0;
        c1[d] = bb;
    }

    float wx0 = w[0][0], wx1 = w[0][1];
    float wy0 = w[1][0], wy1 = w[1][1];
    float wz0 = w[2][0], wz1 = w[2][1];

    float acc0, acc1;

    if (level < N_DQ) {
        // ---- dense fp16 quad: 2 LDG.128 = 8 corners ----
        const uint4* dq = g_dq + p.dq_prefix[level];
        int rr = res;
        uint4 e0 = __ldg(dq + ((c0[0] * rr + c0[1]) * rr + c0[2]));
        uint4 e1 = __ldg(dq + ((c1[0] * rr + c0[1]) * rr + c0[2]));
        float2 a00 = unpack_h2(e0.x), a01 = unpack_h2(e0.y);
        float2 a10 = unpack_h2(e0.z), a11 = unpack_h2(e0.w);
        float2 b00 = unpack_h2(e1.x), b01 = unpack_h2(e1.y);
        float2 b10 = unpack_h2(e1.z), b11 = unpack_h2(e1.w);
        acc0 = (wx0 * (wy0 * (wz0 * a00.x + wz1 * a01.x) +
                       wy1 * (wz0 * a10.x + wz1 * a11.x)) +
                wx1 * (wy0 * (wz0 * b00.x + wz1 * b01.x) +
                       wy1 * (wz0 * b10.x + wz1 * b11.x))) * INV_FSCALE;
        acc1 = (wx0 * (wy0 * (wz0 * a00.y + wz1 * a01.y) +
                       wy1 * (wz0 * a10.y + wz1 * a11.y)) +
                wx1 * (wy0 * (wz0 * b00.y + wz1 * b01.y) +
                       wy1 * (wz0 * b10.y + wz1 * b11.y))) * INV_FSCALE;
    } else {
        // ---- quad hash scheme: usually 2 LDG.128; mismatching dims load
        //      neighbor entries and use their exact words. No fallback. ----
        const uint4* T = g_hq + ((size_t)(level - N_DQ) << HASH_BITS);
        unsigned Dz = p.dA[level];
        unsigned Dy = p.dB[level];

        unsigned hx0 = hash_part(c0[0], fres, 1u);
        unsigned hx1 = hash_part(c1[0], fres, 1u);
        unsigned hy0 = hash_part(c0[1], fres, PRIME2);
        unsigned hy1 = hash_part(c1[1], fres, PRIME2);
        unsigned hz0 = hash_part(c0[2], fres, PRIME3);
        unsigned hz1 = hash_part(c1[2], fres, PRIME3);
        bool okz = (hz1 - hz0) == Dz;
        bool oky = (hy1 - hy0) == Dy;

        float2 v[2][4];   // [xrow][y0z0, y0z1, y1z0, y1z1]
#pragma unroll
        for (int rx = 0; rx < 2; rx++) {
            unsigned hx = rx ? hx1 : hx0;
            uint4 e = __ldg(T + ((hx + hy0 + hz0) & HASH_MASK));
            v[rx][0] = unpack_h2(e.x);
            if (okz & oky) {
                v[rx][1] = unpack_h2(e.y);
                v[rx][2] = unpack_h2(e.z);
                v[rx][3] = unpack_h2(e.w);
            } else {
                if (okz) {
                    v[rx][1] = unpack_h2(e.y);
                } else {
                    uint4 ez = __ldg(T + ((hx + hy0 + hz1) & HASH_MASK));
                    v[rx][1] = unpack_h2(ez.x);
                    if (oky) v[rx][3] = unpack_h2(ez.z);
                }
                if (oky) {
                    v[rx][2] = unpack_h2(e.z);
                } else {
                    uint4 ey = __ldg(T + ((hx + hy1 + hz0) & HASH_MASK));
                    v[rx][2] = unpack_h2(ey.x);
                    if (okz) v[rx][3] = unpack_h2(ey.y);
                }
                if (!okz && !oky) {
                    uint4 ew = __ldg(T + ((hx + hy1 + hz1) & HASH_MASK));
                    v[rx][3] = unpack_h2(ew.x);
                }
            }
        }

        acc0 = (wx0 * (wy0 * (wz0 * v[0][0].x + wz1 * v[0][1].x) +
                       wy1 * (wz0 * v[0][2].x + wz1 * v[0][3].x)) +
                wx1 * (wy0 * (wz0 * v[1][0].x + wz1 * v[1][1].x) +
                       wy1 * (wz0 * v[1][2].x + wz1 * v[1][3].x))) * INV_FSCALE;
        acc1 = (wx0 * (wy0 * (wz0 * v[0][0].y + wz1 * v[0][1].y) +
                       wy1 * (wz0 * v[0][2].y + wz1 * v[0][3].y)) +
                wx1 * (wy0 * (wz0 * v[1][0].y + wz1 * v[1][1].y) +
                       wy1 * (wz0 * v[1][2].y + wz1 * v[1][3].y))) * INV_FSCALE;
    }

    outs[l][2 * level]     = acc0;
    outs[l][2 * level + 1] = acc1;
    __syncthreads();

    // coalesced streaming output: 512 threads write 32 points x 16 levels
    int i = tid >> 4, j = tid & 15;
    int on = n0 + i;
    if (on < n_points) {
        float2 val = make_float2(outs[i][2 * j], outs[i][2 * j + 1]);
        stcs_f2(reinterpret_cast<float2*>(out) + (size_t)on * N_LEVELS + j, val);
    }
}

extern "C" void kernel_launch(void* const* d_in, const int* in_sizes, int n_in,
                              void* d_out, int out_size)
{
    const float* x      = (const float*)d_in[0];
    const float* tables = (const float*)d_in[1];
    float*       out    = (float*)d_out;

    int n_points = in_sizes[0] / 3;

    Params p;
    for (int i = 0; i < N_LEVELS; i++) {
        double r = 16.0 * pow(32.0, (double)i / 15.0);   // host libm pow
        p.res[i] = (int)r;
        p.dA[i] = 0; p.dB[i] = 0;
    }

    // Dense quad levels 0..8 (prefix doubles as entry base offset)
    p.dq_prefix[0] = 0;
    for (int i = 0; i < N_DQ; i++) {
        int cnt = p.res[i] * p.res[i] * p.res[i];
        p.dq_prefix[i + 1] = p.dq_prefix[i] + cnt;
    }

    // Hashed levels 9..15: majority quantizer step dM per level
    for (int lvl = N_DQ; lvl < N_LEVELS; lvl++) {
        unsigned r   = (unsigned)p.res[lvl];
        unsigned d   = 131072u / r;
        unsigned rem = 131072u % r;
        unsigned dM  = (2u * rem >= r) ? d + 1u : d;
        p.dA[lvl] = PRIME3 * dM;   // Dz
        p.dB[lvl] = PRIME2 * dM;   // Dy
    }

    p.total_dq  = p.dq_prefix[N_DQ];
    p.total_hq  = N_HQ << HASH_BITS;
    p.blocks_dq = (p.total_dq + 255) / 256;
    int blocks_hq = (p.total_hq + 255) / 256;

    fill_all_kernel<<<p.blocks_dq + blocks_hq, 256>>>(tables, p);

    int blocks = (n_points + 31) / 32;
    hash_encoding_kernel<<<blocks, 512>>>(x, out, p, n_points);
}

// round 17
// speedup vs baseline: 2.3737x; 2.3737x over previous
#include <cuda_runtime.h>
#include <cuda_fp16.h>
#include <math.h>
#include <stdint.h>

#define N_LEVELS   16
#define N_DQ       9            // levels 0..8: dense fp16 quad grid
#define HASH_BITS  19
#define TABLE_SIZE (1u << HASH_BITS)
#define HASH_MASK  (TABLE_SIZE - 1u)
#define PRIME2     2654435761u
#define PRIME3     805459861u
#define FSCALE     256.0f
#define INV_FSCALE (1.0f / 256.0f)

// Dense fp16 quad grid, levels 0..8: entry(cx,cy,cz) = 16B =
//   {h2(y0z0), h2(y0z1), h2(y1z0), h2(y1z1)}, h2 = half2(256*f0, 256*f1)
#define DQ_CAP 2200000
__device__ uint4 g_dq[DQ_CAP];                       // ~35 MB

// Three-delta fp16 z tables, 5 non-pow2 hashed levels (9,10,11,13,14):
//   T[s] = { h2(tab[s]), h2(tab[s+D0]), h2(tab[s+D1]), h2(tab[s+Dw]) }
#define N_ZP 5
__device__ uint4 g_zp4[(size_t)N_ZP << HASH_BITS];         // ~42 MB

// Pow2-res fp16 quad hash tables, 2 levels (12,15)
#define N_Q2 2
__device__ uint4 g_q2[(size_t)N_Q2 << HASH_BITS];          // ~17 MB

struct Params {
    int      res[N_LEVELS];
    int      kind[N_LEVELS];     // 0 dense quad, 1 three-delta z, 2 pow2 quad
    int      base[N_LEVELS];
    unsigned dA[N_LEVELS];       // zp: P3*d       q2: Dz = P3*step
    unsigned dB[N_LEVELS];       // zp: P3*(d+1)   q2: Dy = P2*step
    int      dq_prefix[N_DQ + 1];
    int      zp_levels[N_ZP];
    int      q2_levels[N_Q2];
    int      blocks_dq, blocks_zp;
    int      total_dq, total_zp, total_q2;
};

// XLA-GPU lowers f32 divide to div.full.f32 (approx). The hash trunc
// amplifies 1-ulp differences into wrong indices; reproduce the instruction.
__device__ __forceinline__ float div_full(float a, float b) {
    float r;
    asm("div.full.f32 %0, %1, %2;" : "=f"(r) : "f"(a), "f"(b));
    return r;
}

__device__ __forceinline__ unsigned hash_part(int c, float fres, unsigned prime) {
    float cfrac = div_full((float)c, fres);
    // (cfrac+1)*0.5*2^18 == (cfrac+1)*2^17 exactly (power-of-2 scalings exact)
    float qf = __fmul_rn(__fadd_rn(cfrac, 1.0f), 131072.0f);
    unsigned q = (unsigned)qf;            // positive -> trunc == astype(int64)
    return q * prime;                      // uint32 wrap OK: 2^19 | 2^32
}

__device__ __forceinline__ unsigned pack_h2(float2 v) {
    __half2 h = __floats2half2_rn(v.x * FSCALE, v.y * FSCALE);
    return *reinterpret_cast<unsigned*>(&h);
}
__device__ __forceinline__ float2 unpack_h2(unsigned u) {
    __half2 h = *reinterpret_cast<__half2*>(&u);
    return __half22float2(h);
}

__device__ __forceinline__ void stcs_f2(float2* p, float2 v) {
    asm volatile("st.global.cs.v2.f32 [%0], {%1, %2};"
                 :: "l"(p), "f"(v.x), "f"(v.y) : "memory");
}

// ---------------------------------------------------------------------------
// Fused fill kernel (block-granular regions; dq shfl stays warp-uniform).
// ---------------------------------------------------------------------------
__global__ void __launch_bounds__(256)
fill_all_kernel(const float* __restrict__ tables, Params p)
{
    int b = blockIdx.x;

    if (b < p.blocks_dq) {
        // ---- dense fp16 quad fill (levels 0..8) ----
        int tid0 = b * 256 + threadIdx.x;
        bool valid = tid0 < p.total_dq;
        int tid = valid ? tid0 : (p.total_dq - 1);

        int level = 0;
#pragma unroll
        for (int i = 0; i < N_DQ; i++)
            if (tid >= p.dq_prefix[i + 1]) level = i + 1;

        int r   = tid - p.dq_prefix[level];
        int res = p.res[level];
        int cz = r % res;
        int t  = r / res;
        int cy = t % res;
        int cx = t / res;
        int cy1 = (cy + 1 == res) ? 0 : cy + 1;

        float fres = (float)res;
        unsigned hx  = hash_part(cx,  fres, 1u);
        unsigned hy  = hash_part(cy,  fres, PRIME2);
        unsigned hy1 = hash_part(cy1, fres, PRIME2);
        unsigned hz  = hash_part(cz,  fres, PRIME3);

        const float2* tab = reinterpret_cast<const float2*>(tables)
                            + (size_t)level * TABLE_SIZE;
        float2 v00 = __ldg(tab + ((hx + hy  + hz) & HASH_MASK));
        float2 v10 = __ldg(tab + ((hx + hy1 + hz) & HASH_MASK));

        int lane = threadIdx.x & 31;
        float a0 = __shfl_down_sync(0xFFFFFFFFu, v00.x, 1);
        float a1 = __shfl_down_sync(0xFFFFFFFFu, v00.y, 1);
        float b0 = __shfl_down_sync(0xFFFFFFFFu, v10.x, 1);
        float b1 = __shfl_down_sync(0xFFFFFFFFu, v10.y, 1);
        float2 v01, v11;
        if (valid && cz < res - 1 && lane < 31 && tid0 + 1 < p.total_dq) {
            v01 = make_float2(a0, a1);
            v11 = make_float2(b0, b1);
        } else {
            int z1 = (cz + 1 == res) ? 0 : cz + 1;
            unsigned hz1 = hash_part(z1, fres, PRIME3);
            v01 = __ldg(tab + ((hx + hy  + hz1) & HASH_MASK));
            v11 = __ldg(tab + ((hx + hy1 + hz1) & HASH_MASK));
        }

        if (valid) {
            uint4 e;
            e.x = pack_h2(v00);
            e.y = pack_h2(v01);
            e.z = pack_h2(v10);
            e.w = pack_h2(v11);
            g_dq[(size_t)p.base[level] + ((cx * res + cy) * res + cz)] = e;
        }
    } else if (b < p.blocks_dq + p.blocks_zp) {
        // ---- three-delta z table fill (coalesced 4-stream reads) ----
        int tid = (b - p.blocks_dq) * 256 + threadIdx.x;
        if (tid >= p.total_zp) return;
        int slot   = tid >> HASH_BITS;
        unsigned s = tid & HASH_MASK;
        int lvl = p.zp_levels[slot];
        int res = p.res[lvl];
        float fres = (float)res;
        unsigned D0 = p.dA[lvl];
        unsigned D1 = p.dB[lvl];
        // wrap delta: hz(0) - hz(res-1), computed with the SAME device hash
        unsigned Dw = PRIME3 * 131072u - hash_part(res - 1, fres, PRIME3);

        const float2* tab = reinterpret_cast<const float2*>(tables)
                            + (size_t)lvl * TABLE_SIZE;
        uint4 e;
        e.x = pack_h2(__ldg(tab + s));
        e.y = pack_h2(__ldg(tab + ((s + D0) & HASH_MASK)));
        e.z = pack_h2(__ldg(tab + ((s + D1) & HASH_MASK)));
        e.w = pack_h2(__ldg(tab + ((s + Dw) & HASH_MASK)));
        g_zp4[((size_t)slot << HASH_BITS) + s] = e;
    } else {
        // ---- pow2 fp16 quad fill (levels 12,15) ----
        int tid = (b - p.blocks_dq - p.blocks_zp) * 256 + threadIdx.x;
        if (tid >= p.total_q2) return;
        int slot   = tid >> HASH_BITS;
        unsigned s = tid & HASH_MASK;
        int lvl = p.q2_levels[slot];
        unsigned Dz = p.dA[lvl];
        unsigned Dy = p.dB[lvl];

        const float2* tab = reinterpret_cast<const float2*>(tables)
                            + (size_t)lvl * TABLE_SIZE;
        uint4 e;
        e.x = pack_h2(__ldg(tab + s));
        e.y = pack_h2(__ldg(tab + ((s + Dz) & HASH_MASK)));
        e.z = pack_h2(__ldg(tab + ((s + Dy) & HASH_MASK)));
        e.w = pack_h2(__ldg(tab + ((s + Dy + Dz) & HASH_MASK)));
        g_q2[((size_t)slot << HASH_BITS) + s] = e;
    }
}

// ---------------------------------------------------------------------------
// Main kernel: block = 32 points x 16 levels (512 threads).
// warp w = level w (BRANCH-UNIFORM), lane = point. Output via smem transpose.
// ---------------------------------------------------------------------------
__global__ void __launch_bounds__(512)
hash_encoding_kernel(const float* __restrict__ x,
                     const float* __restrict__ tables,
                     float* __restrict__ out,
                     Params p,
                     int n_points)
{
    __shared__ float4 xs4[32];        // padded point coords (w unused)
    __shared__ float  outs[32][33];   // stride-33 words: conflict-free writes

    int tid = threadIdx.x;
    int n0  = blockIdx.x * 32;

    if (tid < 96) {
        int gi = n0 * 3 + tid;
        float v = (gi < n_points * 3) ? __ldcs(&x[gi]) : 0.0f;
        reinterpret_cast<float*>(xs4)[(tid / 3) * 4 + (tid % 3)] = v;
    }
    __syncthreads();

    int level = tid >> 5;        // warp index == level (uniform per warp)
    int l     = tid & 31;        // point within block

    float4 pt = xs4[l];          // one conflict-free LDS.128
    float xv[3];
    xv[0] = fminf(fmaxf(pt.x, -1.0f), 1.0f);
    xv[1] = fminf(fmaxf(pt.y, -1.0f), 1.0f);
    xv[2] = fminf(fmaxf(pt.z, -1.0f), 1.0f);

    const int   res  = p.res[level];
    const float fres = (float)res;

    int   c0[3], c1[3];
    float w[3][2];
#pragma unroll
    for (int d = 0; d < 3; d++) {
        float coord = xv[d] * fres;
        float cf    = floorf(coord);
        float lc    = coord - cf;
        int   ci    = (int)cf;
        w[d][0] = 1.0f - lc;
        w[d][1] = lc;
        // ci in [-res, res] -> floor-mod via predicated adds (no int div)
        int a = ci;
        if (a < 0)    a += res;
        if (a >= res) a -= res;
        c0[d] = a;
        int bb = a + 1; if (bb == res) bb = 0;
        c1[d] = bb;
    }

    float wx0 = w[0][0], wx1 = w[0][1];
    float wy0 = w[1][0], wy1 = w[1][1];
    float wz0 = w[2][0], wz1 = w[2][1];

    float acc0 = 0.0f, acc1 = 0.0f;
    int kind = p.kind[level];

    if (kind == 0) {
        // ---- dense fp16 quad: 2 LDG.128 = 8 corners ----
        const uint4* dq = g_dq + p.base[level];
        int rr = res;
        uint4 e0 = __ldg(dq + ((c0[0] * rr + c0[1]) * rr + c0[2]));
        uint4 e1 = __ldg(dq + ((c1[0] * rr + c0[1]) * rr + c0[2]));
        float2 a00 = unpack_h2(e0.x), a01 = unpack_h2(e0.y);
        float2 a10 = unpack_h2(e0.z), a11 = unpack_h2(e0.w);
        float2 b00 = unpack_h2(e1.x), b01 = unpack_h2(e1.y);
        float2 b10 = unpack_h2(e1.z), b11 = unpack_h2(e1.w);
        acc0 = (wx0 * (wy0 * (wz0 * a00.x + wz1 * a01.x) +
                       wy1 * (wz0 * a10.x + wz1 * a11.x)) +
                wx1 * (wy0 * (wz0 * b00.x + wz1 * b01.x) +
                       wy1 * (wz0 * b10.x + wz1 * b11.x))) * INV_FSCALE;
        acc1 = (wx0 * (wy0 * (wz0 * a00.y + wz1 * a01.y) +
                       wy1 * (wz0 * a10.y + wz1 * a11.y)) +
                wx1 * (wy0 * (wz0 * b00.y + wz1 * b01.y) +
                       wy1 * (wz0 * b10.y + wz1 * b11.y))) * INV_FSCALE;
    } else {
        unsigned hx0 = hash_part(c0[0], fres, 1u);
        unsigned hx1 = hash_part(c1[0], fres, 1u);
        unsigned hy0 = hash_part(c0[1], fres, PRIME2);
        unsigned hy1 = hash_part(c1[1], fres, PRIME2);
        unsigned hz0 = hash_part(c0[2], fres, PRIME3);
        unsigned hz1 = hash_part(c1[2], fres, PRIME3);
        unsigned diffz = hz1 - hz0;

        bool done = false;
        if (kind == 1) {
            // ---- three-delta z table: 4 LDG.128, word-select, no branch ----
            bool isA = (diffz == p.dA[level]);
            bool isB = (diffz == p.dB[level]);
            bool isW = (c1[2] == 0);                 // z-wrap
            if (isA | isB | isW) {
                const uint4* zt = g_zp4 + ((size_t)p.base[level]);
                uint4 e00 = __ldg(zt + ((hx0 + hy0 + hz0) & HASH_MASK));
                uint4 e01 = __ldg(zt + ((hx0 + hy1 + hz0) & HASH_MASK));
                uint4 e10 = __ldg(zt + ((hx1 + hy0 + hz0) & HASH_MASK));
                uint4 e11 = __ldg(zt + ((hx1 + hy1 + hz0) & HASH_MASK));
                unsigned s00 = isA ? e00.y : (isB ? e00.z : e00.w);
                unsigned s01 = isA ? e01.y : (isB ? e01.z : e01.w);
                unsigned s10 = isA ? e10.y : (isB ? e10.z : e10.w);
                unsigned s11 = isA ? e11.y : (isB ? e11.z : e11.w);
                float2 p00a = unpack_h2(e00.x), p00b = unpack_h2(s00);
                float2 p01a = unpack_h2(e01.x), p01b = unpack_h2(s01);
                float2 p10a = unpack_h2(e10.x), p10b = unpack_h2(s10);
                float2 p11a = unpack_h2(e11.x), p11b = unpack_h2(s11);
                acc0 = (wx0 * (wy0 * (wz0 * p00a.x + wz1 * p00b.x) +
                               wy1 * (wz0 * p01a.x + wz1 * p01b.x)) +
                        wx1 * (wy0 * (wz0 * p10a.x + wz1 * p10b.x) +
                               wy1 * (wz0 * p11a.x + wz1 * p11b.x))) * INV_FSCALE;
                acc1 = (wx0 * (wy0 * (wz0 * p00a.y + wz1 * p00b.y) +
                               wy1 * (wz0 * p01a.y + wz1 * p01b.y)) +
                        wx1 * (wy0 * (wz0 * p10a.y + wz1 * p10b.y) +
                               wy1 * (wz0 * p11a.y + wz1 * p11b.y))) * INV_FSCALE;
                done = true;
            }
        } else {
            if (diffz == p.dA[level] && (hy1 - hy0) == p.dB[level]) {
                const uint4* qt = g_q2 + (size_t)p.base[level];
                uint4 e0 = __ldg(qt + ((hx0 + hy0 + hz0) & HASH_MASK));
                uint4 e1 = __ldg(qt + ((hx1 + hy0 + hz0) & HASH_MASK));
                float2 a00 = unpack_h2(e0.x), a01 = unpack_h2(e0.y);
                float2 a10 = unpack_h2(e0.z), a11 = unpack_h2(e0.w);
                float2 b00 = unpack_h2(e1.x), b01 = unpack_h2(e1.y);
                float2 b10 = unpack_h2(e1.z), b11 = unpack_h2(e1.w);
                acc0 = (wx0 * (wy0 * (wz0 * a00.x + wz1 * a01.x) +
                               wy1 * (wz0 * a10.x + wz1 * a11.x)) +
                        wx1 * (wy0 * (wz0 * b00.x + wz1 * b01.x) +
                               wy1 * (wz0 * b10.x + wz1 * b11.x))) * INV_FSCALE;
                acc1 = (wx0 * (wy0 * (wz0 * a00.y + wz1 * a01.y) +
                               wy1 * (wz0 * a10.y + wz1 * a11.y)) +
                        wx1 * (wy0 * (wz0 * b00.y + wz1 * b01.y) +
                               wy1 * (wz0 * b10.y + wz1 * b11.y))) * INV_FSCALE;
                done = true;
            }
        }

        if (!done) {
            // ---- exact f32 fallback (rare: q2 wraps, step anomalies) ----
            const float2* tab = reinterpret_cast<const float2*>(tables)
                                + (size_t)level * TABLE_SIZE;
            float2 f000 = __ldg(tab + ((hx0 + hy0 + hz0) & HASH_MASK));
            float2 f001 = __ldg(tab + ((hx0 + hy0 + hz1) & HASH_MASK));
            float2 f010 = __ldg(tab + ((hx0 + hy1 + hz0) & HASH_MASK));
            float2 f011 = __ldg(tab + ((hx0 + hy1 + hz1) & HASH_MASK));
            float2 f100 = __ldg(tab + ((hx1 + hy0 + hz0) & HASH_MASK));
            float2 f101 = __ldg(tab + ((hx1 + hy0 + hz1) & HASH_MASK));
            float2 f110 = __ldg(tab + ((hx1 + hy1 + hz0) & HASH_MASK));
            float2 f111 = __ldg(tab + ((hx1 + hy1 + hz1) & HASH_MASK));
            acc0 = wx0 * (wy0 * (wz0 * f000.x + wz1 * f001.x) +
                          wy1 * (wz0 * f010.x + wz1 * f011.x)) +
                   wx1 * (wy0 * (wz0 * f100.x + wz1 * f101.x) +
                          wy1 * (wz0 * f110.x + wz1 * f111.x));
            acc1 = wx0 * (wy0 * (wz0 * f000.y + wz1 * f001.y) +
                          wy1 * (wz0 * f010.y + wz1 * f011.y)) +
                   wx1 * (wy0 * (wz0 * f100.y + wz1 * f101.y) +
                          wy1 * (wz0 * f110.y + wz1 * f111.y));
        }
    }

    outs[l][2 * level]     = acc0;
    outs[l][2 * level + 1] = acc1;
    __syncthreads();

    // coalesced streaming output: 512 threads write 32 points x 16 levels
    int i = tid >> 4, j = tid & 15;
    int on = n0 + i;
    if (on < n_points) {
        float2 val = make_float2(outs[i][2 * j], outs[i][2 * j + 1]);
        stcs_f2(reinterpret_cast<float2*>(out) + (size_t)on * N_LEVELS + j, val);
    }
}

extern "C" void kernel_launch(void* const* d_in, const int* in_sizes, int n_in,
                              void* d_out, int out_size)
{
    const float* x      = (const float*)d_in[0];
    const float* tables = (const float*)d_in[1];
    float*       out    = (float*)d_out;

    int n_points = in_sizes[0] / 3;

    Params p;
    for (int i = 0; i < N_LEVELS; i++) {
        double r = 16.0 * pow(32.0, (double)i / 15.0);   // host libm pow
        p.res[i] = (int)r;
    }

    int off = 0;
    p.dq_prefix[0] = 0;
    for (int i = 0; i < N_DQ; i++) {
        p.kind[i] = 0;
        p.base[i] = off;
        p.dA[i] = 0; p.dB[i] = 0;
        int cnt = p.res[i] * p.res[i] * p.res[i];
        off += cnt;
        p.dq_prefix[i + 1] = p.dq_prefix[i] + cnt;
    }

    int n_zp = 0, n_q2 = 0;
    for (int lvl = N_DQ; lvl < N_LEVELS; lvl++) {
        int r = p.res[lvl];
        if ((r & (r - 1)) == 0 && n_q2 < N_Q2) {
            unsigned step = 131072u / (unsigned)r;
            p.kind[lvl] = 2;
            p.base[lvl] = n_q2 << HASH_BITS;
            p.dA[lvl] = PRIME3 * step;
            p.dB[lvl] = PRIME2 * step;
            p.q2_levels[n_q2++] = lvl;
        } else {
            unsigned d = 131072u / (unsigned)r;
            p.kind[lvl] = 1;
            p.base[lvl] = n_zp << HASH_BITS;
            p.dA[lvl] = PRIME3 * d;
            p.dB[lvl] = PRIME3 * (d + 1);
            p.zp_levels[n_zp++] = lvl;
        }
    }

    p.total_dq = p.dq_prefix[N_DQ];
    p.total_zp = n_zp << HASH_BITS;
    p.total_q2 = n_q2 << HASH_BITS;
    p.blocks_dq = (p.total_dq + 255) / 256;
    p.blocks_zp = (p.total_zp + 255) / 256;
    int blocks_q2 = (p.total_q2 + 255) / 256;

    int fill_blocks = p.blocks_dq + p.blocks_zp + blocks_q2;
    fill_all_kernel<<<fill_blocks, 256>>>(tables, p);

    int blocks = (n_points + 31) / 32;
    hash_encoding_kernel<<<blocks, 512>>>(x, tables, out, p, n_points);
}